// round 1
// baseline (speedup 1.0000x reference)
#include <cuda_runtime.h>

#define OSC 2048
#define MH  4096
#define NTHR 256

// ---------------- scratch (no allocs allowed) ----------------
__device__ float g_xm[4104];                    // [m_obs(5), h1_s, h2_s] = 4101
__device__ float g_xk1[4100], g_xk2[4100];      // [k, h_s, f_s] = 4097
__device__ float g_xf1[2052], g_xf2[2052];      // [f, f_s] = 2049
__device__ float g_xh1[4100], g_xh2[4100];      // [h, out_m_half, k_s] = 4097
__device__ float g_mnew[MH];
__device__ float g_h1new[OSC], g_h2new[OSC];
__device__ float g_k1new[OSC], g_k2new[OSC];
__device__ float g_f1new[OSC], g_f2new[OSC];

__device__ __forceinline__ float sigm(float v) { return 1.0f / (1.0f + __expf(-v)); }

// block reduction of NS per-thread accumulators; result valid in thread 0
template <int NS>
__device__ __forceinline__ void blockReduce(float (&acc)[NS], float (&out)[NS]) {
    __shared__ float sm[NS][NTHR / 32];
    const int lane = threadIdx.x & 31;
    const int wid  = threadIdx.x >> 5;
#pragma unroll
    for (int s = 0; s < NS; s++) {
        float v = acc[s];
        v += __shfl_down_sync(0xffffffffu, v, 16);
        v += __shfl_down_sync(0xffffffffu, v, 8);
        v += __shfl_down_sync(0xffffffffu, v, 4);
        v += __shfl_down_sync(0xffffffffu, v, 2);
        v += __shfl_down_sync(0xffffffffu, v, 1);
        if (lane == 0) sm[s][wid] = v;
    }
    __syncthreads();
    if (threadIdx.x == 0) {
#pragma unroll
        for (int s = 0; s < NS; s++) {
            float v = 0.0f;
#pragma unroll
            for (int w = 0; w < NTHR / 32; w++) v += sm[s][w];
            out[s] = v;
        }
    }
}

// -------- single-stream GRU unit: one block computes newout[j] --------
__device__ __forceinline__ void gru_unit_single(
    const float* __restrict__ wih, const float* __restrict__ whh,
    const float* __restrict__ bih, const float* __restrict__ bhh,
    const float* __restrict__ xcat, int D,
    const float* __restrict__ hprev, int H, int j,
    float* __restrict__ newout)
{
    float acc[6] = {0, 0, 0, 0, 0, 0};
    const float* wr = wih + (size_t)j * D;
    const float* wz = wih + (size_t)(H + j) * D;
    const float* wn = wih + (size_t)(2 * H + j) * D;
#pragma unroll 4
    for (int d = threadIdx.x; d < D; d += NTHR) {
        float xv = xcat[d];
        acc[0] += wr[d] * xv;
        acc[1] += wz[d] * xv;
        acc[2] += wn[d] * xv;
    }
    const float* ur = whh + (size_t)j * H;
    const float* uz = whh + (size_t)(H + j) * H;
    const float* un = whh + (size_t)(2 * H + j) * H;
#pragma unroll 4
    for (int d = threadIdx.x; d < H; d += NTHR) {
        float hv = hprev[d];
        acc[3] += ur[d] * hv;
        acc[4] += uz[d] * hv;
        acc[5] += un[d] * hv;
    }
    float s[6];
    blockReduce<6>(acc, s);
    if (threadIdx.x == 0) {
        float gir = s[0] + bih[j], giz = s[1] + bih[H + j], gin = s[2] + bih[2 * H + j];
        float ghr = s[3] + bhh[j], ghz = s[4] + bhh[H + j], ghn = s[5] + bhh[2 * H + j];
        float r = sigm(gir + ghr);
        float z = sigm(giz + ghz);
        float n = tanhf(gin + r * ghn);
        newout[j] = (1.0f - z) * n + z * hprev[j];
    }
}

// -------- dual-stream GRU unit: shared weights, two (x, h) pairs --------
__device__ __forceinline__ void gru_unit_dual(
    const float* __restrict__ wih, const float* __restrict__ whh,
    const float* __restrict__ bih, const float* __restrict__ bhh,
    const float* __restrict__ x1, const float* __restrict__ x2, int D,
    const float* __restrict__ h1, const float* __restrict__ h2, int H, int j,
    float* __restrict__ out1, float* __restrict__ out2)
{
    float acc[12] = {0, 0, 0, 0, 0, 0, 0, 0, 0, 0, 0, 0};
    const float* wr = wih + (size_t)j * D;
    const float* wz = wih + (size_t)(H + j) * D;
    const float* wn = wih + (size_t)(2 * H + j) * D;
#pragma unroll 4
    for (int d = threadIdx.x; d < D; d += NTHR) {
        float a = x1[d], b = x2[d];
        float w0 = wr[d], w1 = wz[d], w2 = wn[d];
        acc[0] += w0 * a; acc[1] += w1 * a; acc[2] += w2 * a;
        acc[3] += w0 * b; acc[4] += w1 * b; acc[5] += w2 * b;
    }
    const float* ur = whh + (size_t)j * H;
    const float* uz = whh + (size_t)(H + j) * H;
    const float* un = whh + (size_t)(2 * H + j) * H;
#pragma unroll 4
    for (int d = threadIdx.x; d < H; d += NTHR) {
        float a = h1[d], b = h2[d];
        float w0 = ur[d], w1 = uz[d], w2 = un[d];
        acc[6] += w0 * a; acc[7]  += w1 * a; acc[8]  += w2 * a;
        acc[9] += w0 * b; acc[10] += w1 * b; acc[11] += w2 * b;
    }
    float s[12];
    blockReduce<12>(acc, s);
    if (threadIdx.x == 0) {
        float br = bih[j], bz = bih[H + j], bn = bih[2 * H + j];
        float cr = bhh[j], cz = bhh[H + j], cn = bhh[2 * H + j];
        // stream 1
        {
            float r = sigm(s[0] + br + s[6] + cr);
            float z = sigm(s[1] + bz + s[7] + cz);
            float n = tanhf(s[2] + bn + r * (s[8] + cn));
            out1[j] = (1.0f - z) * n + z * h1[j];
        }
        // stream 2
        {
            float r = sigm(s[3] + br + s[9] + cr);
            float z = sigm(s[4] + bz + s[10] + cz);
            float n = tanhf(s[5] + bn + r * (s[11] + cn));
            out2[j] = (1.0f - z) * n + z * h2[j];
        }
    }
}

// ---------------- K0: build concatenated input vectors ----------------
__global__ __launch_bounds__(NTHR) void k_prep(
    const float* __restrict__ x,
    const float* __restrict__ h1s, const float* __restrict__ h2s,
    const float* __restrict__ k1s, const float* __restrict__ k2s,
    const float* __restrict__ f1s, const float* __restrict__ f2s)
{
    int i = blockIdx.x * blockDim.x + threadIdx.x;
    if (i == 0) {
        g_xm[0] = x[0]; g_xm[1] = x[1]; g_xm[2] = x[8]; g_xm[3] = x[9]; g_xm[4] = x[10];
        g_xk1[0] = x[3]; g_xk2[0] = x[6];
        g_xf1[0] = x[4]; g_xf2[0] = x[7];
        g_xh1[0] = x[2]; g_xh2[0] = x[5];
    }
    if (i < OSC) {
        float h1v = h1s[i], h2v = h2s[i], f1v = f1s[i], f2v = f2s[i];
        g_xm[5 + i]        = h1v;
        g_xm[5 + OSC + i]  = h2v;
        g_xk1[1 + i]       = h1v;
        g_xk1[1 + OSC + i] = f1v;
        g_xk2[1 + i]       = h2v;
        g_xk2[1 + OSC + i] = f2v;
        g_xf1[1 + i]       = f1v;
        g_xf2[1 + i]       = f2v;
        g_xh1[1 + OSC + i] = k1s[i];
        g_xh2[1 + OSC + i] = k2s[i];
    }
}

// ---------------- K1: m (single) + k (dual) + f (dual) GRUs ----------------
__global__ __launch_bounds__(NTHR) void k_gru_mkf(
    const float* __restrict__ m_wih, const float* __restrict__ m_whh,
    const float* __restrict__ m_bih, const float* __restrict__ m_bhh,
    const float* __restrict__ m_s,
    const float* __restrict__ k_wih, const float* __restrict__ k_whh,
    const float* __restrict__ k_bih, const float* __restrict__ k_bhh,
    const float* __restrict__ k1s, const float* __restrict__ k2s,
    const float* __restrict__ f_wih, const float* __restrict__ f_whh,
    const float* __restrict__ f_bih, const float* __restrict__ f_bhh,
    const float* __restrict__ f1s, const float* __restrict__ f2s)
{
    int b = blockIdx.x;
    if (b < MH) {
        gru_unit_single(m_wih, m_whh, m_bih, m_bhh, g_xm, 5 + 2 * OSC, m_s, MH, b, g_mnew);
    } else if (b < MH + OSC) {
        gru_unit_dual(k_wih, k_whh, k_bih, k_bhh, g_xk1, g_xk2, 1 + 2 * OSC,
                      k1s, k2s, OSC, b - MH, g_k1new, g_k2new);
    } else {
        gru_unit_dual(f_wih, f_whh, f_bih, f_bhh, g_xf1, g_xf2, 1 + OSC,
                      f1s, f2s, OSC, b - MH - OSC, g_f1new, g_f2new);
    }
}

// ---------------- K2: out_m = m_out_w @ m_new + b, written into h-cell concats ----------------
__global__ __launch_bounds__(NTHR) void k_mout(
    const float* __restrict__ w, const float* __restrict__ bias)
{
    int r = blockIdx.x;
    const float* wr = w + (size_t)r * MH;
    float acc[1] = {0.0f};
#pragma unroll 4
    for (int d = threadIdx.x; d < MH; d += NTHR) acc[0] += wr[d] * g_mnew[d];
    float s[1];
    blockReduce<1>(acc, s);
    if (threadIdx.x == 0) {
        float v = s[0] + bias[r];
        if (r < OSC) g_xh1[1 + r] = v;
        else         g_xh2[1 + (r - OSC)] = v;
    }
}

// ---------------- K3: h cells (dual-stream) ----------------
__global__ __launch_bounds__(NTHR) void k_gru_h(
    const float* __restrict__ h_wih, const float* __restrict__ h_whh,
    const float* __restrict__ h_bih, const float* __restrict__ h_bhh,
    const float* __restrict__ h1s, const float* __restrict__ h2s)
{
    gru_unit_dual(h_wih, h_whh, h_bih, h_bhh, g_xh1, g_xh2, 1 + 2 * OSC,
                  h1s, h2s, OSC, blockIdx.x, g_h1new, g_h2new);
}

// ---------------- K4: six output dot products ----------------
__global__ __launch_bounds__(NTHR) void k_heads(
    const float* __restrict__ h_ow, const float* __restrict__ h_ob,
    const float* __restrict__ k_ow, const float* __restrict__ k_ob,
    const float* __restrict__ f_ow, const float* __restrict__ f_ob,
    float* __restrict__ out)
{
    int b = blockIdx.x;
    const float* vec;
    const float* w;
    const float* bp;
    switch (b) {
        case 0: vec = g_h1new; w = h_ow; bp = h_ob; break;
        case 1: vec = g_k1new; w = k_ow; bp = k_ob; break;
        case 2: vec = g_f1new; w = f_ow; bp = f_ob; break;
        case 3: vec = g_h2new; w = h_ow; bp = h_ob; break;
        case 4: vec = g_k2new; w = k_ow; bp = k_ob; break;
        default: vec = g_f2new; w = f_ow; bp = f_ob; break;
    }
    float acc[1] = {0.0f};
    for (int d = threadIdx.x; d < OSC; d += NTHR) acc[0] += w[d] * vec[d];
    float s[1];
    blockReduce<1>(acc, s);
    if (threadIdx.x == 0) out[b] = s[0] + bp[0];
}

// ---------------- launch ----------------
extern "C" void kernel_launch(void* const* d_in, const int* in_sizes, int n_in,
                              void* d_out, int out_size)
{
    const float* x      = (const float*)d_in[0];
    const float* m_s    = (const float*)d_in[1];
    const float* h1_s   = (const float*)d_in[2];
    const float* h2_s   = (const float*)d_in[3];
    const float* k1_s   = (const float*)d_in[4];
    const float* k2_s   = (const float*)d_in[5];
    const float* f1_s   = (const float*)d_in[6];
    const float* f2_s   = (const float*)d_in[7];
    const float* m_wih  = (const float*)d_in[8];
    const float* m_whh  = (const float*)d_in[9];
    const float* m_bih  = (const float*)d_in[10];
    const float* m_bhh  = (const float*)d_in[11];
    const float* m_ow   = (const float*)d_in[12];
    const float* m_ob   = (const float*)d_in[13];
    const float* h_wih  = (const float*)d_in[14];
    const float* h_whh  = (const float*)d_in[15];
    const float* h_bih  = (const float*)d_in[16];
    const float* h_bhh  = (const float*)d_in[17];
    const float* h_ow   = (const float*)d_in[18];
    const float* h_ob   = (const float*)d_in[19];
    const float* k_wih  = (const float*)d_in[20];
    const float* k_whh  = (const float*)d_in[21];
    const float* k_bih  = (const float*)d_in[22];
    const float* k_bhh  = (const float*)d_in[23];
    const float* k_ow   = (const float*)d_in[24];
    const float* k_ob   = (const float*)d_in[25];
    const float* f_wih  = (const float*)d_in[26];
    const float* f_whh  = (const float*)d_in[27];
    const float* f_bih  = (const float*)d_in[28];
    const float* f_bhh  = (const float*)d_in[29];
    const float* f_ow   = (const float*)d_in[30];
    const float* f_ob   = (const float*)d_in[31];
    float* out = (float*)d_out;

    k_prep<<<(OSC + NTHR - 1) / NTHR, NTHR>>>(x, h1_s, h2_s, k1_s, k2_s, f1_s, f2_s);
    k_gru_mkf<<<MH + 2 * OSC, NTHR>>>(m_wih, m_whh, m_bih, m_bhh, m_s,
                                      k_wih, k_whh, k_bih, k_bhh, k1_s, k2_s,
                                      f_wih, f_whh, f_bih, f_bhh, f1_s, f2_s);
    k_mout<<<MH, NTHR>>>(m_ow, m_ob);
    k_gru_h<<<OSC, NTHR>>>(h_wih, h_whh, h_bih, h_bhh, h1_s, h2_s);
    k_heads<<<6, NTHR>>>(h_ow, h_ob, k_ow, k_ob, f_ow, f_ob, out);
}

// round 2
// speedup vs baseline: 1.1095x; 1.1095x over previous
#include <cuda_runtime.h>

#define OSC 2048
#define MH  4096
#define NTHR 256

// ---------------- scratch (no allocs allowed) ----------------
__device__ __align__(16) float g_xm[4104];               // [m_obs(5), h1_s, h2_s] = 4101
__device__ __align__(16) float g_xk1[4100], g_xk2[4100]; // [k, h_s, f_s] = 4097
__device__ __align__(16) float g_xf1[2052], g_xf2[2052]; // [f, f_s] = 2049
__device__ __align__(16) float g_xh1[4100], g_xh2[4100]; // [h, out_m_half, k_s] = 4097
__device__ __align__(16) float g_mnew[MH];
__device__ __align__(16) float g_h1new[OSC], g_h2new[OSC];
__device__ __align__(16) float g_k1new[OSC], g_k2new[OSC];
__device__ __align__(16) float g_f1new[OSC], g_f2new[OSC];

__device__ __forceinline__ float sigm(float v) { return 1.0f / (1.0f + __expf(-v)); }

// block reduction of NS per-thread accumulators; result valid in thread 0
template <int NS>
__device__ __forceinline__ void blockReduce(float (&acc)[NS], float (&out)[NS]) {
    __shared__ float sm[NS][NTHR / 32];
    const int lane = threadIdx.x & 31;
    const int wid  = threadIdx.x >> 5;
#pragma unroll
    for (int s = 0; s < NS; s++) {
        float v = acc[s];
        v += __shfl_down_sync(0xffffffffu, v, 16);
        v += __shfl_down_sync(0xffffffffu, v, 8);
        v += __shfl_down_sync(0xffffffffu, v, 4);
        v += __shfl_down_sync(0xffffffffu, v, 2);
        v += __shfl_down_sync(0xffffffffu, v, 1);
        if (lane == 0) sm[s][wid] = v;
    }
    __syncthreads();
    if (threadIdx.x == 0) {
#pragma unroll
        for (int s = 0; s < NS; s++) {
            float v = 0.0f;
#pragma unroll
            for (int w = 0; w < NTHR / 32; w++) v += sm[s][w];
            out[s] = v;
        }
    }
}

// -------- single-stream GRU unit (vectorized): one block computes newout[j] --------
__device__ __forceinline__ void gru_unit_single(
    const float* __restrict__ wih, const float* __restrict__ whh,
    const float* __restrict__ bih, const float* __restrict__ bhh,
    const float* __restrict__ xcat, int D,
    const float* __restrict__ hprev, int H, int j,
    float* __restrict__ newout)
{
    float acc[6] = {0, 0, 0, 0, 0, 0};
    const size_t jD = (size_t)j * D;
    const float* wr = wih + jD;
    const float* wz = wih + (size_t)(H + j) * D;     // same align class as wr (H*D % 4 == 0)
    const float* wn = wih + (size_t)(2 * H + j) * D;
    const int head = (int)((4 - (jD & 3)) & 3);
    const int nvec = (D - head) >> 2;
    const int tail = D - head - (nvec << 2);

    if (threadIdx.x < (unsigned)head) {
        int d = threadIdx.x;
        float xv = xcat[d];
        acc[0] += wr[d] * xv; acc[1] += wz[d] * xv; acc[2] += wn[d] * xv;
    }
#pragma unroll 4
    for (int c = threadIdx.x; c < nvec; c += NTHR) {
        int d = head + (c << 2);
        float4 a = *(const float4*)(wr + d);
        float4 b = *(const float4*)(wz + d);
        float4 e = *(const float4*)(wn + d);
        float x0 = xcat[d], x1 = xcat[d + 1], x2 = xcat[d + 2], x3 = xcat[d + 3];
        acc[0] += a.x * x0 + a.y * x1 + a.z * x2 + a.w * x3;
        acc[1] += b.x * x0 + b.y * x1 + b.z * x2 + b.w * x3;
        acc[2] += e.x * x0 + e.y * x1 + e.z * x2 + e.w * x3;
    }
    if (threadIdx.x < (unsigned)tail) {
        int d = head + (nvec << 2) + threadIdx.x;
        float xv = xcat[d];
        acc[0] += wr[d] * xv; acc[1] += wz[d] * xv; acc[2] += wn[d] * xv;
    }

    // w_hh rows: H % 4 == 0 -> fully aligned, hprev aligned
    const float* ur = whh + (size_t)j * H;
    const float* uz = whh + (size_t)(H + j) * H;
    const float* un = whh + (size_t)(2 * H + j) * H;
    const int nvh = H >> 2;
#pragma unroll 4
    for (int c = threadIdx.x; c < nvh; c += NTHR) {
        int d = c << 2;
        float4 a = *(const float4*)(ur + d);
        float4 b = *(const float4*)(uz + d);
        float4 e = *(const float4*)(un + d);
        float4 h = *(const float4*)(hprev + d);
        acc[3] += a.x * h.x + a.y * h.y + a.z * h.z + a.w * h.w;
        acc[4] += b.x * h.x + b.y * h.y + b.z * h.z + b.w * h.w;
        acc[5] += e.x * h.x + e.y * h.y + e.z * h.z + e.w * h.w;
    }

    float s[6];
    blockReduce<6>(acc, s);
    if (threadIdx.x == 0) {
        float gir = s[0] + bih[j], giz = s[1] + bih[H + j], gin = s[2] + bih[2 * H + j];
        float ghr = s[3] + bhh[j], ghz = s[4] + bhh[H + j], ghn = s[5] + bhh[2 * H + j];
        float r = sigm(gir + ghr);
        float z = sigm(giz + ghz);
        float n = tanhf(gin + r * ghn);
        newout[j] = (1.0f - z) * n + z * hprev[j];
    }
}

// -------- dual-stream GRU unit (vectorized): shared weights, two (x, h) pairs --------
__device__ __forceinline__ void gru_unit_dual(
    const float* __restrict__ wih, const float* __restrict__ whh,
    const float* __restrict__ bih, const float* __restrict__ bhh,
    const float* __restrict__ x1, const float* __restrict__ x2, int D,
    const float* __restrict__ h1, const float* __restrict__ h2, int H, int j,
    float* __restrict__ out1, float* __restrict__ out2)
{
    float acc[12] = {0, 0, 0, 0, 0, 0, 0, 0, 0, 0, 0, 0};
    const size_t jD = (size_t)j * D;
    const float* wr = wih + jD;
    const float* wz = wih + (size_t)(H + j) * D;
    const float* wn = wih + (size_t)(2 * H + j) * D;
    const int head = (int)((4 - (jD & 3)) & 3);
    const int nvec = (D - head) >> 2;
    const int tail = D - head - (nvec << 2);

    if (threadIdx.x < (unsigned)head) {
        int d = threadIdx.x;
        float a = x1[d], b = x2[d];
        float w0 = wr[d], w1 = wz[d], w2 = wn[d];
        acc[0] += w0 * a; acc[1] += w1 * a; acc[2] += w2 * a;
        acc[3] += w0 * b; acc[4] += w1 * b; acc[5] += w2 * b;
    }
#pragma unroll 4
    for (int c = threadIdx.x; c < nvec; c += NTHR) {
        int d = head + (c << 2);
        float4 a = *(const float4*)(wr + d);
        float4 b = *(const float4*)(wz + d);
        float4 e = *(const float4*)(wn + d);
        float p0 = x1[d], p1 = x1[d + 1], p2 = x1[d + 2], p3 = x1[d + 3];
        float q0 = x2[d], q1 = x2[d + 1], q2 = x2[d + 2], q3 = x2[d + 3];
        acc[0] += a.x * p0 + a.y * p1 + a.z * p2 + a.w * p3;
        acc[1] += b.x * p0 + b.y * p1 + b.z * p2 + b.w * p3;
        acc[2] += e.x * p0 + e.y * p1 + e.z * p2 + e.w * p3;
        acc[3] += a.x * q0 + a.y * q1 + a.z * q2 + a.w * q3;
        acc[4] += b.x * q0 + b.y * q1 + b.z * q2 + b.w * q3;
        acc[5] += e.x * q0 + e.y * q1 + e.z * q2 + e.w * q3;
    }
    if (threadIdx.x < (unsigned)tail) {
        int d = head + (nvec << 2) + threadIdx.x;
        float a = x1[d], b = x2[d];
        float w0 = wr[d], w1 = wz[d], w2 = wn[d];
        acc[0] += w0 * a; acc[1] += w1 * a; acc[2] += w2 * a;
        acc[3] += w0 * b; acc[4] += w1 * b; acc[5] += w2 * b;
    }

    const float* ur = whh + (size_t)j * H;
    const float* uz = whh + (size_t)(H + j) * H;
    const float* un = whh + (size_t)(2 * H + j) * H;
    const int nvh = H >> 2;
#pragma unroll 4
    for (int c = threadIdx.x; c < nvh; c += NTHR) {
        int d = c << 2;
        float4 a = *(const float4*)(ur + d);
        float4 b = *(const float4*)(uz + d);
        float4 e = *(const float4*)(un + d);
        float4 ha = *(const float4*)(h1 + d);
        float4 hb = *(const float4*)(h2 + d);
        acc[6]  += a.x * ha.x + a.y * ha.y + a.z * ha.z + a.w * ha.w;
        acc[7]  += b.x * ha.x + b.y * ha.y + b.z * ha.z + b.w * ha.w;
        acc[8]  += e.x * ha.x + e.y * ha.y + e.z * ha.z + e.w * ha.w;
        acc[9]  += a.x * hb.x + a.y * hb.y + a.z * hb.z + a.w * hb.w;
        acc[10] += b.x * hb.x + b.y * hb.y + b.z * hb.z + b.w * hb.w;
        acc[11] += e.x * hb.x + e.y * hb.y + e.z * hb.z + e.w * hb.w;
    }

    float s[12];
    blockReduce<12>(acc, s);
    if (threadIdx.x == 0) {
        float br = bih[j], bz = bih[H + j], bn = bih[2 * H + j];
        float cr = bhh[j], cz = bhh[H + j], cn = bhh[2 * H + j];
        {
            float r = sigm(s[0] + br + s[6] + cr);
            float z = sigm(s[1] + bz + s[7] + cz);
            float n = tanhf(s[2] + bn + r * (s[8] + cn));
            out1[j] = (1.0f - z) * n + z * h1[j];
        }
        {
            float r = sigm(s[3] + br + s[9] + cr);
            float z = sigm(s[4] + bz + s[10] + cz);
            float n = tanhf(s[5] + bn + r * (s[11] + cn));
            out2[j] = (1.0f - z) * n + z * h2[j];
        }
    }
}

// ---------------- K0: build concatenated input vectors ----------------
__global__ __launch_bounds__(NTHR) void k_prep(
    const float* __restrict__ x,
    const float* __restrict__ h1s, const float* __restrict__ h2s,
    const float* __restrict__ k1s, const float* __restrict__ k2s,
    const float* __restrict__ f1s, const float* __restrict__ f2s)
{
    int i = blockIdx.x * blockDim.x + threadIdx.x;
    if (i == 0) {
        g_xm[0] = x[0]; g_xm[1] = x[1]; g_xm[2] = x[8]; g_xm[3] = x[9]; g_xm[4] = x[10];
        g_xk1[0] = x[3]; g_xk2[0] = x[6];
        g_xf1[0] = x[4]; g_xf2[0] = x[7];
        g_xh1[0] = x[2]; g_xh2[0] = x[5];
    }
    if (i < OSC) {
        float h1v = h1s[i], h2v = h2s[i], f1v = f1s[i], f2v = f2s[i];
        g_xm[5 + i]        = h1v;
        g_xm[5 + OSC + i]  = h2v;
        g_xk1[1 + i]       = h1v;
        g_xk1[1 + OSC + i] = f1v;
        g_xk2[1 + i]       = h2v;
        g_xk2[1 + OSC + i] = f2v;
        g_xf1[1 + i]       = f1v;
        g_xf2[1 + i]       = f2v;
        g_xh1[1 + OSC + i] = k1s[i];
        g_xh2[1 + OSC + i] = k2s[i];
    }
}

// ---------------- K1: m (single) + k (dual) + f (dual) GRUs ----------------
__global__ __launch_bounds__(NTHR) void k_gru_mkf(
    const float* __restrict__ m_wih, const float* __restrict__ m_whh,
    const float* __restrict__ m_bih, const float* __restrict__ m_bhh,
    const float* __restrict__ m_s,
    const float* __restrict__ k_wih, const float* __restrict__ k_whh,
    const float* __restrict__ k_bih, const float* __restrict__ k_bhh,
    const float* __restrict__ k1s, const float* __restrict__ k2s,
    const float* __restrict__ f_wih, const float* __restrict__ f_whh,
    const float* __restrict__ f_bih, const float* __restrict__ f_bhh,
    const float* __restrict__ f1s, const float* __restrict__ f2s)
{
    int b = blockIdx.x;
    if (b < MH) {
        gru_unit_single(m_wih, m_whh, m_bih, m_bhh, g_xm, 5 + 2 * OSC, m_s, MH, b, g_mnew);
    } else if (b < MH + OSC) {
        gru_unit_dual(k_wih, k_whh, k_bih, k_bhh, g_xk1, g_xk2, 1 + 2 * OSC,
                      k1s, k2s, OSC, b - MH, g_k1new, g_k2new);
    } else {
        gru_unit_dual(f_wih, f_whh, f_bih, f_bhh, g_xf1, g_xf2, 1 + OSC,
                      f1s, f2s, OSC, b - MH - OSC, g_f1new, g_f2new);
    }
}

// ---------------- K2: out_m = m_out_w @ m_new + b, written into h-cell concats ----------------
__global__ __launch_bounds__(NTHR) void k_mout(
    const float* __restrict__ w, const float* __restrict__ bias)
{
    int r = blockIdx.x;
    const float* wr = w + (size_t)r * MH;   // MH % 4 == 0 -> aligned
    float acc[1] = {0.0f};
#pragma unroll 4
    for (int c = threadIdx.x; c < (MH >> 2); c += NTHR) {
        int d = c << 2;
        float4 a = *(const float4*)(wr + d);
        float4 m = *(const float4*)(g_mnew + d);
        acc[0] += a.x * m.x + a.y * m.y + a.z * m.z + a.w * m.w;
    }
    float s[1];
    blockReduce<1>(acc, s);
    if (threadIdx.x == 0) {
        float v = s[0] + bias[r];
        if (r < OSC) g_xh1[1 + r] = v;
        else         g_xh2[1 + (r - OSC)] = v;
    }
}

// ---------------- K3: h cells (dual-stream) ----------------
__global__ __launch_bounds__(NTHR) void k_gru_h(
    const float* __restrict__ h_wih, const float* __restrict__ h_whh,
    const float* __restrict__ h_bih, const float* __restrict__ h_bhh,
    const float* __restrict__ h1s, const float* __restrict__ h2s)
{
    gru_unit_dual(h_wih, h_whh, h_bih, h_bhh, g_xh1, g_xh2, 1 + 2 * OSC,
                  h1s, h2s, OSC, blockIdx.x, g_h1new, g_h2new);
}

// ---------------- K4: six output dot products ----------------
__global__ __launch_bounds__(NTHR) void k_heads(
    const float* __restrict__ h_ow, const float* __restrict__ h_ob,
    const float* __restrict__ k_ow, const float* __restrict__ k_ob,
    const float* __restrict__ f_ow, const float* __restrict__ f_ob,
    float* __restrict__ out)
{
    int b = blockIdx.x;
    const float* vec;
    const float* w;
    const float* bp;
    switch (b) {
        case 0: vec = g_h1new; w = h_ow; bp = h_ob; break;
        case 1: vec = g_k1new; w = k_ow; bp = k_ob; break;
        case 2: vec = g_f1new; w = f_ow; bp = f_ob; break;
        case 3: vec = g_h2new; w = h_ow; bp = h_ob; break;
        case 4: vec = g_k2new; w = k_ow; bp = k_ob; break;
        default: vec = g_f2new; w = f_ow; bp = f_ob; break;
    }
    float acc[1] = {0.0f};
#pragma unroll 4
    for (int c = threadIdx.x; c < (OSC >> 2); c += NTHR) {
        int d = c << 2;
        float4 a = *(const float4*)(w + d);
        float4 v = *(const float4*)(vec + d);
        acc[0] += a.x * v.x + a.y * v.y + a.z * v.z + a.w * v.w;
    }
    float s[1];
    blockReduce<1>(acc, s);
    if (threadIdx.x == 0) out[b] = s[0] + bp[0];
}

// ---------------- launch ----------------
extern "C" void kernel_launch(void* const* d_in, const int* in_sizes, int n_in,
                              void* d_out, int out_size)
{
    const float* x      = (const float*)d_in[0];
    const float* m_s    = (const float*)d_in[1];
    const float* h1_s   = (const float*)d_in[2];
    const float* h2_s   = (const float*)d_in[3];
    const float* k1_s   = (const float*)d_in[4];
    const float* k2_s   = (const float*)d_in[5];
    const float* f1_s   = (const float*)d_in[6];
    const float* f2_s   = (const float*)d_in[7];
    const float* m_wih  = (const float*)d_in[8];
    const float* m_whh  = (const float*)d_in[9];
    const float* m_bih  = (const float*)d_in[10];
    const float* m_bhh  = (const float*)d_in[11];
    const float* m_ow   = (const float*)d_in[12];
    const float* m_ob   = (const float*)d_in[13];
    const float* h_wih  = (const float*)d_in[14];
    const float* h_whh  = (const float*)d_in[15];
    const float* h_bih  = (const float*)d_in[16];
    const float* h_bhh  = (const float*)d_in[17];
    const float* h_ow   = (const float*)d_in[18];
    const float* h_ob   = (const float*)d_in[19];
    const float* k_wih  = (const float*)d_in[20];
    const float* k_whh  = (const float*)d_in[21];
    const float* k_bih  = (const float*)d_in[22];
    const float* k_bhh  = (const float*)d_in[23];
    const float* k_ow   = (const float*)d_in[24];
    const float* k_ob   = (const float*)d_in[25];
    const float* f_wih  = (const float*)d_in[26];
    const float* f_whh  = (const float*)d_in[27];
    const float* f_bih  = (const float*)d_in[28];
    const float* f_bhh  = (const float*)d_in[29];
    const float* f_ow   = (const float*)d_in[30];
    const float* f_ob   = (const float*)d_in[31];
    float* out = (float*)d_out;

    k_prep<<<(OSC + NTHR - 1) / NTHR, NTHR>>>(x, h1_s, h2_s, k1_s, k2_s, f1_s, f2_s);
    k_gru_mkf<<<MH + 2 * OSC, NTHR>>>(m_wih, m_whh, m_bih, m_bhh, m_s,
                                      k_wih, k_whh, k_bih, k_bhh, k1_s, k2_s,
                                      f_wih, f_whh, f_bih, f_bhh, f1_s, f2_s);
    k_mout<<<MH, NTHR>>>(m_ow, m_ob);
    k_gru_h<<<OSC, NTHR>>>(h_wih, h_whh, h_bih, h_bhh, h1_s, h2_s);
    k_heads<<<6, NTHR>>>(h_ow, h_ob, k_ow, k_ob, f_ow, f_ob, out);
}

// round 3
// speedup vs baseline: 1.2932x; 1.1656x over previous
#include <cuda_runtime.h>

#define OSC 2048
#define MH  4096
#define NTHR 256

#define XM_L  4101
#define XM_P  4104
#define XK_P  4100
#define XF_P  2052
#define XH_P  4100

// ---------------- scratch (no allocs allowed) ----------------
// 4 alignment-class shifted copies of each concatenated input vector.
// Copy for class h is stored with offset o = (4-h)&3 so that element index h
// lands on a 16B boundary: buf[h*PAD + o + i] = xcat[i].
__device__ __align__(16) float g_xm [4 * XM_P];
__device__ __align__(16) float g_xk1[4 * XK_P], g_xk2[4 * XK_P];
__device__ __align__(16) float g_xf1[4 * XF_P], g_xf2[4 * XF_P];
__device__ __align__(16) float g_xh1[4 * XH_P], g_xh2[4 * XH_P];
__device__ __align__(16) float g_mnew[MH];
__device__ __align__(16) float g_h1new[OSC], g_h2new[OSC];
__device__ __align__(16) float g_k1new[OSC], g_k2new[OSC];
__device__ __align__(16) float g_f1new[OSC], g_f2new[OSC];

__device__ __forceinline__ float sigm(float v) { return 1.0f / (1.0f + __expf(-v)); }
__device__ __forceinline__ int cls_off(int h) { return (4 - h) & 3; }

// streaming (evict-first) 128-bit weight load
__device__ __forceinline__ float4 ldw(const float* p) {
    return __ldcs(reinterpret_cast<const float4*>(p));
}
__device__ __forceinline__ float4 ldx(const float* p) {
    return *reinterpret_cast<const float4*>(p);
}
__device__ __forceinline__ float dot4(float4 a, float4 b) {
    return a.x * b.x + a.y * b.y + a.z * b.z + a.w * b.w;
}

// block reduction of NS per-thread accumulators; result valid in thread 0
template <int NS>
__device__ __forceinline__ void blockReduce(float (&acc)[NS], float (&out)[NS]) {
    __shared__ float sm[NS][NTHR / 32];
    const int lane = threadIdx.x & 31;
    const int wid  = threadIdx.x >> 5;
#pragma unroll
    for (int s = 0; s < NS; s++) {
        float v = acc[s];
        v += __shfl_down_sync(0xffffffffu, v, 16);
        v += __shfl_down_sync(0xffffffffu, v, 8);
        v += __shfl_down_sync(0xffffffffu, v, 4);
        v += __shfl_down_sync(0xffffffffu, v, 2);
        v += __shfl_down_sync(0xffffffffu, v, 1);
        if (lane == 0) sm[s][wid] = v;
    }
    __syncthreads();
    if (threadIdx.x == 0) {
#pragma unroll
        for (int s = 0; s < NS; s++) {
            float v = 0.0f;
#pragma unroll
            for (int w = 0; w < NTHR / 32; w++) v += sm[s][w];
            out[s] = v;
        }
    }
}

// -------- single-stream GRU unit: block computes newout[j]; D % 4 == 1 --------
__device__ __forceinline__ void gru_unit_single(
    const float* __restrict__ wih, const float* __restrict__ whh,
    const float* __restrict__ bih, const float* __restrict__ bhh,
    const float* __restrict__ xbufs, int pad, int D,
    const float* __restrict__ hprev, int H, int j,
    float* __restrict__ newout)
{
    float acc[6] = {0, 0, 0, 0, 0, 0};
    const int head = (4 - (j & 3)) & 3;          // = (4 - (j*D)%4) % 4 since D%4==1
    const float* xc = xbufs + head * pad + cls_off(head);  // xc[i] == xcat[i], &xc[head] aligned
    const float* wr = wih + (size_t)j * D;
    const float* wz = wih + (size_t)(H + j) * D;
    const float* wn = wih + (size_t)(2 * H + j) * D;
    const int nvec = (D - head) >> 2;
    const int tail = D - head - (nvec << 2);

    if (threadIdx.x < (unsigned)head) {
        int d = threadIdx.x;
        float xv = xc[d];
        acc[0] += wr[d] * xv; acc[1] += wz[d] * xv; acc[2] += wn[d] * xv;
    }
    int c = threadIdx.x;
    for (; c + NTHR < nvec; c += 2 * NTHR) {
        int d0 = head + (c << 2);
        int d1 = d0 + (NTHR << 2);
        float4 a0 = ldw(wr + d0), b0 = ldw(wz + d0), e0 = ldw(wn + d0);
        float4 a1 = ldw(wr + d1), b1 = ldw(wz + d1), e1 = ldw(wn + d1);
        float4 x0 = ldx(xc + d0), x1 = ldx(xc + d1);
        acc[0] += dot4(a0, x0); acc[1] += dot4(b0, x0); acc[2] += dot4(e0, x0);
        acc[0] += dot4(a1, x1); acc[1] += dot4(b1, x1); acc[2] += dot4(e1, x1);
    }
    if (c < nvec) {
        int d0 = head + (c << 2);
        float4 a0 = ldw(wr + d0), b0 = ldw(wz + d0), e0 = ldw(wn + d0);
        float4 x0 = ldx(xc + d0);
        acc[0] += dot4(a0, x0); acc[1] += dot4(b0, x0); acc[2] += dot4(e0, x0);
    }
    if (threadIdx.x < (unsigned)tail) {
        int d = head + (nvec << 2) + threadIdx.x;
        float xv = xc[d];
        acc[0] += wr[d] * xv; acc[1] += wz[d] * xv; acc[2] += wn[d] * xv;
    }

    const float* ur = whh + (size_t)j * H;
    const float* uz = whh + (size_t)(H + j) * H;
    const float* un = whh + (size_t)(2 * H + j) * H;
    const int nvh = H >> 2;
    c = threadIdx.x;
    for (; c + NTHR < nvh; c += 2 * NTHR) {
        int d0 = c << 2, d1 = d0 + (NTHR << 2);
        float4 a0 = ldw(ur + d0), b0 = ldw(uz + d0), e0 = ldw(un + d0);
        float4 a1 = ldw(ur + d1), b1 = ldw(uz + d1), e1 = ldw(un + d1);
        float4 h0 = ldx(hprev + d0), h1v = ldx(hprev + d1);
        acc[3] += dot4(a0, h0); acc[4] += dot4(b0, h0); acc[5] += dot4(e0, h0);
        acc[3] += dot4(a1, h1v); acc[4] += dot4(b1, h1v); acc[5] += dot4(e1, h1v);
    }
    if (c < nvh) {
        int d0 = c << 2;
        float4 a0 = ldw(ur + d0), b0 = ldw(uz + d0), e0 = ldw(un + d0);
        float4 h0 = ldx(hprev + d0);
        acc[3] += dot4(a0, h0); acc[4] += dot4(b0, h0); acc[5] += dot4(e0, h0);
    }

    float s[6];
    blockReduce<6>(acc, s);
    if (threadIdx.x == 0) {
        float r = sigm(s[0] + bih[j] + s[3] + bhh[j]);
        float z = sigm(s[1] + bih[H + j] + s[4] + bhh[H + j]);
        float n = tanhf(s[2] + bih[2 * H + j] + r * (s[5] + bhh[2 * H + j]));
        newout[j] = (1.0f - z) * n + z * hprev[j];
    }
}

// -------- dual-stream GRU unit: shared weights, two (x, h) pairs; D % 4 == 1 --------
__device__ __forceinline__ void gru_unit_dual(
    const float* __restrict__ wih, const float* __restrict__ whh,
    const float* __restrict__ bih, const float* __restrict__ bhh,
    const float* __restrict__ x1bufs, const float* __restrict__ x2bufs, int pad, int D,
    const float* __restrict__ h1, const float* __restrict__ h2, int H, int j,
    float* __restrict__ out1, float* __restrict__ out2)
{
    float acc[12] = {0, 0, 0, 0, 0, 0, 0, 0, 0, 0, 0, 0};
    const int head = (4 - (j & 3)) & 3;
    const int off  = head * pad + cls_off(head);
    const float* x1c = x1bufs + off;
    const float* x2c = x2bufs + off;
    const float* wr = wih + (size_t)j * D;
    const float* wz = wih + (size_t)(H + j) * D;
    const float* wn = wih + (size_t)(2 * H + j) * D;
    const int nvec = (D - head) >> 2;
    const int tail = D - head - (nvec << 2);

    if (threadIdx.x < (unsigned)head) {
        int d = threadIdx.x;
        float a = x1c[d], b = x2c[d];
        float w0 = wr[d], w1 = wz[d], w2 = wn[d];
        acc[0] += w0 * a; acc[1] += w1 * a; acc[2] += w2 * a;
        acc[3] += w0 * b; acc[4] += w1 * b; acc[5] += w2 * b;
    }
    int c = threadIdx.x;
    for (; c + NTHR < nvec; c += 2 * NTHR) {
        int d0 = head + (c << 2), d1 = d0 + (NTHR << 2);
        float4 a0 = ldw(wr + d0), b0 = ldw(wz + d0), e0 = ldw(wn + d0);
        float4 a1 = ldw(wr + d1), b1 = ldw(wz + d1), e1 = ldw(wn + d1);
        float4 p0 = ldx(x1c + d0), q0 = ldx(x2c + d0);
        float4 p1 = ldx(x1c + d1), q1 = ldx(x2c + d1);
        acc[0] += dot4(a0, p0); acc[1] += dot4(b0, p0); acc[2] += dot4(e0, p0);
        acc[3] += dot4(a0, q0); acc[4] += dot4(b0, q0); acc[5] += dot4(e0, q0);
        acc[0] += dot4(a1, p1); acc[1] += dot4(b1, p1); acc[2] += dot4(e1, p1);
        acc[3] += dot4(a1, q1); acc[4] += dot4(b1, q1); acc[5] += dot4(e1, q1);
    }
    if (c < nvec) {
        int d0 = head + (c << 2);
        float4 a0 = ldw(wr + d0), b0 = ldw(wz + d0), e0 = ldw(wn + d0);
        float4 p0 = ldx(x1c + d0), q0 = ldx(x2c + d0);
        acc[0] += dot4(a0, p0); acc[1] += dot4(b0, p0); acc[2] += dot4(e0, p0);
        acc[3] += dot4(a0, q0); acc[4] += dot4(b0, q0); acc[5] += dot4(e0, q0);
    }
    if (threadIdx.x < (unsigned)tail) {
        int d = head + (nvec << 2) + threadIdx.x;
        float a = x1c[d], b = x2c[d];
        float w0 = wr[d], w1 = wz[d], w2 = wn[d];
        acc[0] += w0 * a; acc[1] += w1 * a; acc[2] += w2 * a;
        acc[3] += w0 * b; acc[4] += w1 * b; acc[5] += w2 * b;
    }

    const float* ur = whh + (size_t)j * H;
    const float* uz = whh + (size_t)(H + j) * H;
    const float* un = whh + (size_t)(2 * H + j) * H;
    const int nvh = H >> 2;
    c = threadIdx.x;
    for (; c + NTHR < nvh; c += 2 * NTHR) {
        int d0 = c << 2, d1 = d0 + (NTHR << 2);
        float4 a0 = ldw(ur + d0), b0 = ldw(uz + d0), e0 = ldw(un + d0);
        float4 a1 = ldw(ur + d1), b1 = ldw(uz + d1), e1 = ldw(un + d1);
        float4 p0 = ldx(h1 + d0), q0 = ldx(h2 + d0);
        float4 p1 = ldx(h1 + d1), q1 = ldx(h2 + d1);
        acc[6] += dot4(a0, p0); acc[7]  += dot4(b0, p0); acc[8]  += dot4(e0, p0);
        acc[9] += dot4(a0, q0); acc[10] += dot4(b0, q0); acc[11] += dot4(e0, q0);
        acc[6] += dot4(a1, p1); acc[7]  += dot4(b1, p1); acc[8]  += dot4(e1, p1);
        acc[9] += dot4(a1, q1); acc[10] += dot4(b1, q1); acc[11] += dot4(e1, q1);
    }
    if (c < nvh) {
        int d0 = c << 2;
        float4 a0 = ldw(ur + d0), b0 = ldw(uz + d0), e0 = ldw(un + d0);
        float4 p0 = ldx(h1 + d0), q0 = ldx(h2 + d0);
        acc[6] += dot4(a0, p0); acc[7]  += dot4(b0, p0); acc[8]  += dot4(e0, p0);
        acc[9] += dot4(a0, q0); acc[10] += dot4(b0, q0); acc[11] += dot4(e0, q0);
    }

    float s[12];
    blockReduce<12>(acc, s);
    if (threadIdx.x == 0) {
        float br = bih[j], bz = bih[H + j], bn = bih[2 * H + j];
        float cr = bhh[j], cz = bhh[H + j], cn = bhh[2 * H + j];
        {
            float r = sigm(s[0] + br + s[6] + cr);
            float z = sigm(s[1] + bz + s[7] + cz);
            float n = tanhf(s[2] + bn + r * (s[8] + cn));
            out1[j] = (1.0f - z) * n + z * h1[j];
        }
        {
            float r = sigm(s[3] + br + s[9] + cr);
            float z = sigm(s[4] + bz + s[10] + cz);
            float n = tanhf(s[5] + bn + r * (s[11] + cn));
            out2[j] = (1.0f - z) * n + z * h2[j];
        }
    }
}

// ---------------- K0: build shifted copies of concatenated input vectors ----------------
__global__ __launch_bounds__(NTHR) void k_prep(
    const float* __restrict__ x,
    const float* __restrict__ h1s, const float* __restrict__ h2s,
    const float* __restrict__ k1s, const float* __restrict__ k2s,
    const float* __restrict__ f1s, const float* __restrict__ f2s)
{
    int i = blockIdx.x * blockDim.x + threadIdx.x;
    if (i == 0) {
#pragma unroll
        for (int h = 0; h < 4; h++) {
            int o = cls_off(h);
            g_xm [h * XM_P + o + 0] = x[0];
            g_xm [h * XM_P + o + 1] = x[1];
            g_xm [h * XM_P + o + 2] = x[8];
            g_xm [h * XM_P + o + 3] = x[9];
            g_xm [h * XM_P + o + 4] = x[10];
            g_xk1[h * XK_P + o] = x[3]; g_xk2[h * XK_P + o] = x[6];
            g_xf1[h * XF_P + o] = x[4]; g_xf2[h * XF_P + o] = x[7];
            g_xh1[h * XH_P + o] = x[2]; g_xh2[h * XH_P + o] = x[5];
        }
    }
    if (i < OSC) {
        float h1v = h1s[i], h2v = h2s[i], f1v = f1s[i], f2v = f2s[i];
        float k1v = k1s[i], k2v = k2s[i];
#pragma unroll
        for (int h = 0; h < 4; h++) {
            int o = cls_off(h);
            g_xm [h * XM_P + o + 5 + i]        = h1v;
            g_xm [h * XM_P + o + 5 + OSC + i]  = h2v;
            g_xk1[h * XK_P + o + 1 + i]        = h1v;
            g_xk1[h * XK_P + o + 1 + OSC + i]  = f1v;
            g_xk2[h * XK_P + o + 1 + i]        = h2v;
            g_xk2[h * XK_P + o + 1 + OSC + i]  = f2v;
            g_xf1[h * XF_P + o + 1 + i]        = f1v;
            g_xf2[h * XF_P + o + 1 + i]        = f2v;
            g_xh1[h * XH_P + o + 1 + OSC + i]  = k1v;
            g_xh2[h * XH_P + o + 1 + OSC + i]  = k2v;
        }
    }
}

// ---------------- K1: m (single) + k (dual) + f (dual) GRUs ----------------
__global__ __launch_bounds__(NTHR) void k_gru_mkf(
    const float* __restrict__ m_wih, const float* __restrict__ m_whh,
    const float* __restrict__ m_bih, const float* __restrict__ m_bhh,
    const float* __restrict__ m_s,
    const float* __restrict__ k_wih, const float* __restrict__ k_whh,
    const float* __restrict__ k_bih, const float* __restrict__ k_bhh,
    const float* __restrict__ k1s, const float* __restrict__ k2s,
    const float* __restrict__ f_wih, const float* __restrict__ f_whh,
    const float* __restrict__ f_bih, const float* __restrict__ f_bhh,
    const float* __restrict__ f1s, const float* __restrict__ f2s)
{
    int b = blockIdx.x;
    if (b < MH) {
        gru_unit_single(m_wih, m_whh, m_bih, m_bhh, g_xm, XM_P, 5 + 2 * OSC,
                        m_s, MH, b, g_mnew);
    } else if (b < MH + OSC) {
        gru_unit_dual(k_wih, k_whh, k_bih, k_bhh, g_xk1, g_xk2, XK_P, 1 + 2 * OSC,
                      k1s, k2s, OSC, b - MH, g_k1new, g_k2new);
    } else {
        gru_unit_dual(f_wih, f_whh, f_bih, f_bhh, g_xf1, g_xf2, XF_P, 1 + OSC,
                      f1s, f2s, OSC, b - MH - OSC, g_f1new, g_f2new);
    }
}

// ---------------- K2: out_m row r -> all shifted copies of h-cell concats ----------------
__global__ __launch_bounds__(NTHR) void k_mout(
    const float* __restrict__ w, const float* __restrict__ bias)
{
    int r = blockIdx.x;
    const float* wr = w + (size_t)r * MH;   // MH % 4 == 0 -> aligned
    float acc[1] = {0.0f};
    int c = threadIdx.x;
    const int nv = MH >> 2;
    for (; c + NTHR < nv; c += 2 * NTHR) {
        int d0 = c << 2, d1 = d0 + (NTHR << 2);
        float4 a0 = ldw(wr + d0), a1 = ldw(wr + d1);
        float4 m0 = ldx(g_mnew + d0), m1 = ldx(g_mnew + d1);
        acc[0] += dot4(a0, m0) + dot4(a1, m1);
    }
    if (c < nv) {
        int d0 = c << 2;
        acc[0] += dot4(ldw(wr + d0), ldx(g_mnew + d0));
    }
    float s[1];
    blockReduce<1>(acc, s);
    if (threadIdx.x == 0) {
        float v = s[0] + bias[r];
        if (r < OSC) {
#pragma unroll
            for (int h = 0; h < 4; h++) g_xh1[h * XH_P + cls_off(h) + 1 + r] = v;
        } else {
            int rr = r - OSC;
#pragma unroll
            for (int h = 0; h < 4; h++) g_xh2[h * XH_P + cls_off(h) + 1 + rr] = v;
        }
    }
}

// ---------------- K3: h cells (dual-stream) ----------------
__global__ __launch_bounds__(NTHR) void k_gru_h(
    const float* __restrict__ h_wih, const float* __restrict__ h_whh,
    const float* __restrict__ h_bih, const float* __restrict__ h_bhh,
    const float* __restrict__ h1s, const float* __restrict__ h2s)
{
    gru_unit_dual(h_wih, h_whh, h_bih, h_bhh, g_xh1, g_xh2, XH_P, 1 + 2 * OSC,
                  h1s, h2s, OSC, blockIdx.x, g_h1new, g_h2new);
}

// ---------------- K4: six output dot products ----------------
__global__ __launch_bounds__(NTHR) void k_heads(
    const float* __restrict__ h_ow, const float* __restrict__ h_ob,
    const float* __restrict__ k_ow, const float* __restrict__ k_ob,
    const float* __restrict__ f_ow, const float* __restrict__ f_ob,
    float* __restrict__ out)
{
    int b = blockIdx.x;
    const float* vec;
    const float* w;
    const float* bp;
    switch (b) {
        case 0: vec = g_h1new; w = h_ow; bp = h_ob; break;
        case 1: vec = g_k1new; w = k_ow; bp = k_ob; break;
        case 2: vec = g_f1new; w = f_ow; bp = f_ob; break;
        case 3: vec = g_h2new; w = h_ow; bp = h_ob; break;
        case 4: vec = g_k2new; w = k_ow; bp = k_ob; break;
        default: vec = g_f2new; w = f_ow; bp = f_ob; break;
    }
    float acc[1] = {0.0f};
#pragma unroll 4
    for (int c = threadIdx.x; c < (OSC >> 2); c += NTHR) {
        int d = c << 2;
        acc[0] += dot4(ldx(w + d), ldx(vec + d));
    }
    float s[1];
    blockReduce<1>(acc, s);
    if (threadIdx.x == 0) out[b] = s[0] + bp[0];
}

// ---------------- launch ----------------
extern "C" void kernel_launch(void* const* d_in, const int* in_sizes, int n_in,
                              void* d_out, int out_size)
{
    const float* x      = (const float*)d_in[0];
    const float* m_s    = (const float*)d_in[1];
    const float* h1_s   = (const float*)d_in[2];
    const float* h2_s   = (const float*)d_in[3];
    const float* k1_s   = (const float*)d_in[4];
    const float* k2_s   = (const float*)d_in[5];
    const float* f1_s   = (const float*)d_in[6];
    const float* f2_s   = (const float*)d_in[7];
    const float* m_wih  = (const float*)d_in[8];
    const float* m_whh  = (const float*)d_in[9];
    const float* m_bih  = (const float*)d_in[10];
    const float* m_bhh  = (const float*)d_in[11];
    const float* m_ow   = (const float*)d_in[12];
    const float* m_ob   = (const float*)d_in[13];
    const float* h_wih  = (const float*)d_in[14];
    const float* h_whh  = (const float*)d_in[15];
    const float* h_bih  = (const float*)d_in[16];
    const float* h_bhh  = (const float*)d_in[17];
    const float* h_ow   = (const float*)d_in[18];
    const float* h_ob   = (const float*)d_in[19];
    const float* k_wih  = (const float*)d_in[20];
    const float* k_whh  = (const float*)d_in[21];
    const float* k_bih  = (const float*)d_in[22];
    const float* k_bhh  = (const float*)d_in[23];
    const float* k_ow   = (const float*)d_in[24];
    const float* k_ob   = (const float*)d_in[25];
    const float* f_wih  = (const float*)d_in[26];
    const float* f_whh  = (const float*)d_in[27];
    const float* f_bih  = (const float*)d_in[28];
    const float* f_bhh  = (const float*)d_in[29];
    const float* f_ow   = (const float*)d_in[30];
    const float* f_ob   = (const float*)d_in[31];
    float* out = (float*)d_out;

    k_prep<<<(OSC + NTHR - 1) / NTHR, NTHR>>>(x, h1_s, h2_s, k1_s, k2_s, f1_s, f2_s);
    k_gru_mkf<<<MH + 2 * OSC, NTHR>>>(m_wih, m_whh, m_bih, m_bhh, m_s,
                                      k_wih, k_whh, k_bih, k_bhh, k1_s, k2_s,
                                      f_wih, f_whh, f_bih, f_bhh, f1_s, f2_s);
    k_mout<<<MH, NTHR>>>(m_ow, m_ob);
    k_gru_h<<<OSC, NTHR>>>(h_wih, h_whh, h_bih, h_bhh, h1_s, h2_s);
    k_heads<<<6, NTHR>>>(h_ow, h_ob, k_ow, k_ob, f_ow, f_ob, out);
}